// round 14
// baseline (speedup 1.0000x reference)
#include <cuda_runtime.h>
#include <cuda_fp16.h>
#include <math.h>
#include <cstdint>

#define SEQ 2048
#define DM  1024
#define HD  64
#define NH  16
#define NB  2
#define MTOT (NB*SEQ)     // 4096
#define GK   (2*DM)       // 2048 = 2-term fp16 split K (GEMM1 q-columns)
#define QW   (3*DM)       // qkv output row stride
#define BK   32
#define LDA  40           // gemm smem row stride (fp16)
#define LDR  72           // attn smem row stride (fp16)
#define QSC  (0.125f * 1.44269504088896f)   // head scale * log2(e): exp2 softmax

// scratch (__device__ globals: allocation-free rule)
__device__ __half  g_qkvh [(size_t)MTOT * QW];    // qkv hi (q pre-scaled to log2 domain)
__device__ __half  g_qkvl [(size_t)MTOT * QW];    // qkv lo (only q part written/read)
__device__ __half  g_xb   [(size_t)MTOT * GK];    // A' of GEMM1 [hi,lo]
__device__ __half  g_wqkvb[(size_t)QW   * GK];    // B' of GEMM1 [wh,wh]
__device__ __half  g_woutb[(size_t)DM   * DM];    // B of GEMM3 [wh] (K=1024)
__device__ __half  g_attnb[(size_t)MTOT * DM];    // A of GEMM3 [hi] (K=1024)

__device__ __forceinline__ uint32_t smem_u32(const void* p) {
    uint32_t a;
    asm("{ .reg .u64 t; cvta.to.shared.u64 t, %1; cvt.u32.u64 %0, t; }"
        : "=r"(a) : "l"(p));
    return a;
}

__device__ __forceinline__ void split2h(float x, float y, uint32_t& hi, uint32_t& lo) {
    __half2 h, l;
    h.x = __float2half(x);
    h.y = __float2half(y);
    l.x = __float2half(x - __half2float(h.x));
    l.y = __float2half(y - __half2float(h.y));
    hi = *(uint32_t*)&h;
    lo = *(uint32_t*)&l;
}

__device__ __forceinline__ uint32_t cvt2h(float x, float y) {
    __half2 h;
    h.x = __float2half(x);
    h.y = __float2half(y);
    return *(uint32_t*)&h;
}

#define MMA_OP(d, a, b)                                                        \
    asm volatile(                                                              \
        "mma.sync.aligned.m16n8k16.row.col.f32.f16.f16.f32 "                   \
        "{%0,%1,%2,%3}, {%4,%5,%6,%7}, {%8,%9}, {%0,%1,%2,%3};"                \
        : "+f"((d)[0]), "+f"((d)[1]), "+f"((d)[2]), "+f"((d)[3])               \
        : "r"((a)[0]), "r"((a)[1]), "r"((a)[2]), "r"((a)[3]),                  \
          "r"((b)[0]), "r"((b)[1]))

#define LDSM_X4(r, addr)                                                       \
    asm volatile("ldmatrix.sync.aligned.m8n8.x4.shared.b16 {%0,%1,%2,%3}, [%4];" \
                 : "=r"((r)[0]), "=r"((r)[1]), "=r"((r)[2]), "=r"((r)[3])      \
                 : "r"(addr))

#define LDSM_X4_T(r, addr)                                                     \
    asm volatile("ldmatrix.sync.aligned.m8n8.x4.trans.shared.b16 {%0,%1,%2,%3}, [%4];" \
                 : "=r"((r)[0]), "=r"((r)[1]), "=r"((r)[2]), "=r"((r)[3])      \
                 : "r"(addr))

#define CP16(dst, src)                                                         \
    asm volatile("cp.async.cg.shared.global [%0], [%1], 16;" :: "r"(dst), "l"(src))

// ---------------------------------------------------------------------------
// fp32 -> fp16 split; A-style = [hi, lo] (stride GK), B-style = [wh, wh]
// ---------------------------------------------------------------------------
template<bool ASTYLE>
__global__ __launch_bounds__(256)
void split_kernel(const float* __restrict__ src, __half* __restrict__ dst,
                  int n2) {   // n2 = n/2
    int i = blockIdx.x * 256 + threadIdx.x;
    if (i >= n2) return;
    int e = i * 2;
    int r = e >> 10, k = e & 1023;
    float2 v = *(const float2*)(src + e);
    uint32_t h2, l2;
    split2h(v.x, v.y, h2, l2);
    __half* d = dst + (size_t)r * GK + k;
    if (ASTYLE) { *(uint32_t*)(d) = h2; *(uint32_t*)(d + 1024) = l2; }
    else        { *(uint32_t*)(d) = h2; *(uint32_t*)(d + 1024) = h2; }
}

// plain fp32 -> fp16 convert (row-major, same shape)
__global__ __launch_bounds__(256)
void cvt_kernel(const float* __restrict__ src, __half* __restrict__ dst, int n2) {
    int i = blockIdx.x * 256 + threadIdx.x;
    if (i >= n2) return;
    float2 v = *(const float2*)(src + i * 2);
    *(uint32_t*)(dst + i * 2) = cvt2h(v.x, v.y);
}

// ---------------------------------------------------------------------------
// fp16 NT GEMM via mma.sync — R3 geometry/schedule (best measured):
// 128x128 CTA, 8 warps (64x32 warp tile), BK=32, 2-stage cp.async,
// wait_group 1 + dual __syncthreads per chunk.
// SPLIT mode (GEMM1): k and v column blocks (bn>=1024) use only the hi half
// of K (1-term); lo-plane written for q columns only. q pre-scaled by QSC.
// ---------------------------------------------------------------------------
template<int NTOT, int KTOT, bool SPLIT>
__global__ __launch_bounds__(256)
void mma_gemm(const __half* __restrict__ A,
              const __half* __restrict__ B,
              float* __restrict__ C,
              __half* __restrict__ Ch,
              __half* __restrict__ Cl) {
    __shared__ __half As[2 * 128 * LDA];
    __shared__ __half Bs[2 * 128 * LDA];
    const int tid = threadIdx.x;
    const int lane = tid & 31;
    const int wid = tid >> 5;
    const int wm = wid & 1;
    const int wn = wid >> 1;
    const int bm = blockIdx.y * 128;
    const int bn = blockIdx.x * 128;

    // k and v columns need only the hi (1-term) half of K
    const int nch = (SPLIT && bn >= 1024) ? (KTOT / 2 / BK) : (KTOT / BK);

    float acc[4][4][4];
#pragma unroll
    for (int i = 0; i < 4; i++)
#pragma unroll
        for (int j = 0; j < 4; j++)
#pragma unroll
            for (int k = 0; k < 4; k++) acc[i][j][k] = 0.f;

    const int lrow = tid >> 1;
    const int lcol = (tid & 1) * 16;
    const __half* Ag = A + (size_t)(bm + lrow) * KTOT + lcol;
    const __half* Bg = B + (size_t)(bn + lrow) * KTOT + lcol;
    const uint32_t a_smem = smem_u32(As);
    const uint32_t b_smem = smem_u32(Bs);
    const uint32_t st_off = (uint32_t)(lrow * LDA + lcol) * 2;
    const uint32_t stage_b = 128 * LDA * 2;

#define LOAD_STAGE(s, kc) do {                                                 \
        const char* ga = (const char*)(Ag + (size_t)(kc) * BK);                \
        const char* gb = (const char*)(Bg + (size_t)(kc) * BK);                \
        uint32_t sa = a_smem + (s) * stage_b + st_off;                         \
        uint32_t sb = b_smem + (s) * stage_b + st_off;                         \
        CP16(sa, ga); CP16(sa + 16, ga + 16);                                  \
        CP16(sb, gb); CP16(sb + 16, gb + 16);                                  \
        asm volatile("cp.async.commit_group;" ::: "memory");                   \
    } while (0)

    const int lr16 = lane & 15;
    const int lhi  = lane >> 4;

    LOAD_STAGE(0, 0);

    for (int c = 0; c < nch; ++c) {
        const int s = c & 1;
        if (c + 1 < nch) {
            LOAD_STAGE(s ^ 1, c + 1);
            asm volatile("cp.async.wait_group 1;" ::: "memory");
        } else {
            asm volatile("cp.async.wait_group 0;" ::: "memory");
        }
        __syncthreads();

        const uint32_t ab = a_smem + s * stage_b;
        const uint32_t bb = b_smem + s * stage_b;
#pragma unroll
        for (int kk = 0; kk < 2; kk++) {
            uint32_t a[4][4];
#pragma unroll
            for (int mi = 0; mi < 4; mi++) {
                uint32_t addr = ab + (uint32_t)((wm * 64 + mi * 16 + lr16) * LDA
                                                + kk * 16 + lhi * 8) * 2;
                LDSM_X4(a[mi], addr);
            }
            uint32_t b[4][2];
#pragma unroll
            for (int g = 0; g < 2; g++) {
                uint32_t r[4];
                uint32_t addr = bb + (uint32_t)((wn * 32 + g * 16 + lr16) * LDA
                                                + kk * 16 + lhi * 8) * 2;
                LDSM_X4(r, addr);
                b[g * 2 + 0][0] = r[0]; b[g * 2 + 0][1] = r[2];
                b[g * 2 + 1][0] = r[1]; b[g * 2 + 1][1] = r[3];
            }
#pragma unroll
            for (int mi = 0; mi < 4; mi++)
#pragma unroll
                for (int ni = 0; ni < 4; ni++)
                    MMA_OP(acc[mi][ni], a[mi], b[ni]);
        }
        __syncthreads();
    }
#undef LOAD_STAGE

    const int er = lane >> 2;
    const int ec = (lane & 3) * 2;
#pragma unroll
    for (int mi = 0; mi < 4; mi++) {
#pragma unroll
        for (int ni = 0; ni < 4; ni++) {
            const int row = bm + wm * 64 + mi * 16 + er;
            const int col = bn + wn * 32 + ni * 8 + ec;
            if (SPLIT) {
                const float sc = (col < 1024) ? QSC : 1.0f;   // log2-domain q scale
                const bool wlo = (col < 1024);                // lo plane: q only
                uint32_t h2, l2;
                split2h(acc[mi][ni][0] * sc, acc[mi][ni][1] * sc, h2, l2);
                *(uint32_t*)(Ch + (size_t)row * NTOT + col) = h2;
                if (wlo) *(uint32_t*)(Cl + (size_t)row * NTOT + col) = l2;
                split2h(acc[mi][ni][2] * sc, acc[mi][ni][3] * sc, h2, l2);
                *(uint32_t*)(Ch + (size_t)(row + 8) * NTOT + col) = h2;
                if (wlo) *(uint32_t*)(Cl + (size_t)(row + 8) * NTOT + col) = l2;
            } else {
                float2 v0 = make_float2(acc[mi][ni][0], acc[mi][ni][1]);
                float2 v1 = make_float2(acc[mi][ni][2], acc[mi][ni][3]);
                *(float2*)(C + (size_t)row * NTOT + col) = v0;
                *(float2*)(C + (size_t)(row + 8) * NTOT + col) = v1;
            }
        }
    }
}

// ---------------------------------------------------------------------------
// Tensor-core flash attention (causal), fp16, exp2-domain softmax.
// S = (qh+ql)·kh  (2-term q: exp-amplified path keeps precision)
// O = ph·vh       (1-term: post-softmax linear path)
// Block = 256 q-rows x (head,batch), 16 warps (16 rows each), 512 threads.
// K/V 64-key hi tiles double-buffered via cp.async. Descending-qt order.
// ---------------------------------------------------------------------------
#define NEG_BIG (-1e30f)

__global__ __launch_bounds__(512)
void attn_kernel(const __half* __restrict__ qkvh,
                 const __half* __restrict__ qkvl,
                 __half* __restrict__ attnb) {
    extern __shared__ __half smk[];
    const uint32_t s_base = smem_u32(smk);
    const uint32_t tpb = 64 * LDR * 2;   // 9216 B per tensor
    const uint32_t spb = 2 * tpb;        // per stage (Kh, Vh)

    const int tid  = threadIdx.x;
    const int lane = tid & 31;
    const int wid  = tid >> 5;           // 0..15
    const int qt = (int)gridDim.x - 1 - (int)blockIdx.x;  // heaviest first
    const int h  = blockIdx.y;
    const int b  = blockIdx.z;

    const int lr16 = lane & 15;
    const int lhi  = lane >> 4;
    const int er   = lane >> 2;
    const int ec   = (lane & 3) * 2;

    const int qrow0 = qt * 256 + wid * 16;

    // ---- Q hi/lo fragments (pre-scaled to log2 domain) held in regs ----
    uint32_t qh[4][4], ql[4][4];
    {
        const __half* qbh = qkvh + ((size_t)b * SEQ) * QW + h * HD;
        const __half* qbl = qkvl + ((size_t)b * SEQ) * QW + h * HD;
#pragma unroll
        for (int kc = 0; kc < 4; kc++) {
#pragma unroll
            for (int p = 0; p < 4; p++) {
                const int r = qrow0 + er + (p & 1) * 8;
                const int c = kc * 16 + ec + (p >> 1) * 8;
                qh[kc][p] = *(const uint32_t*)(qbh + (size_t)r * QW + c);
                ql[kc][p] = *(const uint32_t*)(qbl + (size_t)r * QW + c);
            }
        }
    }

    float m0 = NEG_BIG, m1 = NEG_BIG, l0 = 0.f, l1 = 0.f;
    float acc[8][4];
#pragma unroll
    for (int nb = 0; nb < 8; nb++)
#pragma unroll
        for (int j = 0; j < 4; j++) acc[nb][j] = 0.f;

    // KV load: 512 threads -> row tid>>3 (0..63), 16B chunk tid&7 of Kh and Vh
    const int krow = tid >> 3;
    const int kch8 = tid & 7;

#define KV_LOAD(s, jt_) do {                                                   \
        size_t gr = ((size_t)b * SEQ + (size_t)(jt_) * 64 + krow) * QW         \
                    + h * HD + kch8 * 8;                                       \
        const char* khg = (const char*)(qkvh + gr + 1024);                     \
        const char* vhg = (const char*)(qkvh + gr + 2048);                     \
        uint32_t d = s_base + (s) * spb + (uint32_t)(krow * LDR * 2 + kch8 * 16); \
        CP16(d + 0 * tpb, khg);                                                \
        CP16(d + 1 * tpb, vhg);                                                \
        asm volatile("cp.async.commit_group;" ::: "memory");                   \
    } while (0)

    const int ntiles = 4 * qt + 4;
    KV_LOAD(0, 0);

    for (int jt = 0; jt < ntiles; ++jt) {
        const int s = jt & 1;
        asm volatile("cp.async.wait_group 0;" ::: "memory");
        __syncthreads();
        if (jt + 1 < ntiles) KV_LOAD(s ^ 1, jt + 1);

        if (jt * 64 <= qrow0 + 15) {   // warp has unmasked work in this tile
            const uint32_t kh_s = s_base + s * spb;
            const uint32_t vh_s = kh_s + tpb;

            // ---- S = Qs @ Kh^T (qh + ql terms), log2-domain logits ----
            float sv[8][4];
#pragma unroll
            for (int nb = 0; nb < 8; nb++)
#pragma unroll
                for (int j = 0; j < 4; j++) sv[nb][j] = 0.f;

#pragma unroll
            for (int kc = 0; kc < 4; kc++) {
                uint32_t bh[8][2];
#pragma unroll
                for (int g = 0; g < 4; g++) {
                    uint32_t r4[4];
                    uint32_t off = (uint32_t)((g * 16 + lr16) * LDR
                                              + kc * 16 + lhi * 8) * 2;
                    LDSM_X4(r4, kh_s + off);
                    bh[2*g][0] = r4[0]; bh[2*g][1] = r4[2];
                    bh[2*g+1][0] = r4[1]; bh[2*g+1][1] = r4[3];
                }
#pragma unroll
                for (int nb = 0; nb < 8; nb++) {
                    MMA_OP(sv[nb], qh[kc], bh[nb]);
                    MMA_OP(sv[nb], ql[kc], bh[nb]);
                }
            }

            // ---- causal mask where tile crosses diagonal ----
            if (jt * 64 + 63 > qrow0) {
                const int r0g = qrow0 + er, r1g = r0g + 8;
#pragma unroll
                for (int nb = 0; nb < 8; nb++) {
                    const int c0g = jt * 64 + nb * 8 + ec;
                    if (c0g     > r0g) sv[nb][0] = NEG_BIG;
                    if (c0g + 1 > r0g) sv[nb][1] = NEG_BIG;
                    if (c0g     > r1g) sv[nb][2] = NEG_BIG;
                    if (c0g + 1 > r1g) sv[nb][3] = NEG_BIG;
                }
            }

            // ---- online softmax (base-2) ----
            float mt0 = NEG_BIG, mt1 = NEG_BIG;
#pragma unroll
            for (int nb = 0; nb < 8; nb++) {
                mt0 = fmaxf(mt0, fmaxf(sv[nb][0], sv[nb][1]));
                mt1 = fmaxf(mt1, fmaxf(sv[nb][2], sv[nb][3]));
            }
            mt0 = fmaxf(mt0, __shfl_xor_sync(0xffffffffu, mt0, 1));
            mt0 = fmaxf(mt0, __shfl_xor_sync(0xffffffffu, mt0, 2));
            mt1 = fmaxf(mt1, __shfl_xor_sync(0xffffffffu, mt1, 1));
            mt1 = fmaxf(mt1, __shfl_xor_sync(0xffffffffu, mt1, 2));
            const float nm0 = fmaxf(m0, mt0), nm1 = fmaxf(m1, mt1);
            const float a0 = exp2f(m0 - nm0), a1 = exp2f(m1 - nm1);
            m0 = nm0; m1 = nm1;
            float sum0 = 0.f, sum1 = 0.f;
#pragma unroll
            for (int nb = 0; nb < 8; nb++) {
                sv[nb][0] = exp2f(sv[nb][0] - nm0);
                sv[nb][1] = exp2f(sv[nb][1] - nm0);
                sv[nb][2] = exp2f(sv[nb][2] - nm1);
                sv[nb][3] = exp2f(sv[nb][3] - nm1);
                sum0 += sv[nb][0] + sv[nb][1];
                sum1 += sv[nb][2] + sv[nb][3];
            }
            sum0 += __shfl_xor_sync(0xffffffffu, sum0, 1);
            sum0 += __shfl_xor_sync(0xffffffffu, sum0, 2);
            sum1 += __shfl_xor_sync(0xffffffffu, sum1, 1);
            sum1 += __shfl_xor_sync(0xffffffffu, sum1, 2);
            l0 = l0 * a0 + sum0;
            l1 = l1 * a1 + sum1;
#pragma unroll
            for (int nb = 0; nb < 8; nb++) {
                acc[nb][0] *= a0; acc[nb][1] *= a0;
                acc[nb][2] *= a1; acc[nb][3] *= a1;
            }

            // ---- pack P into fp16 A-fragments (hi only) ----
            uint32_t ah[4][4];
#pragma unroll
            for (int g = 0; g < 4; g++) {
                ah[g][0] = cvt2h(sv[2*g][0],   sv[2*g][1]);
                ah[g][1] = cvt2h(sv[2*g][2],   sv[2*g][3]);
                ah[g][2] = cvt2h(sv[2*g+1][0], sv[2*g+1][1]);
                ah[g][3] = cvt2h(sv[2*g+1][2], sv[2*g+1][3]);
            }

            // ---- O += Ph @ Vh (1-term, linear path) ----
#pragma unroll
            for (int g = 0; g < 4; g++) {
                uint32_t bvh[8][2];
#pragma unroll
                for (int du = 0; du < 4; du++) {
                    uint32_t r4[4];
                    uint32_t off = (uint32_t)((g * 16 + lr16) * LDR
                                              + du * 16 + lhi * 8) * 2;
                    LDSM_X4_T(r4, vh_s + off);
                    bvh[2*du][0] = r4[0]; bvh[2*du][1] = r4[1];
                    bvh[2*du+1][0] = r4[2]; bvh[2*du+1][1] = r4[3];
                }
#pragma unroll
                for (int nb = 0; nb < 8; nb++)
                    MMA_OP(acc[nb], ah[g], bvh[nb]);
            }
        }
    }
#undef KV_LOAD

    // ---- epilogue: normalize, fp16 hi write (K=1024 for GEMM3) ----
    const float inv0 = 1.f / l0, inv1 = 1.f / l1;
#pragma unroll
    for (int nb = 0; nb < 8; nb++) {
        const int col = h * HD + nb * 8 + ec;
        __half* p0 = attnb + ((size_t)b * SEQ + qrow0 + er) * DM + col;
        *(uint32_t*)(p0) = cvt2h(acc[nb][0] * inv0, acc[nb][1] * inv0);
        __half* p1 = p0 + (size_t)8 * DM;
        *(uint32_t*)(p1) = cvt2h(acc[nb][2] * inv1, acc[nb][3] * inv1);
    }
}

// ---------------------------------------------------------------------------
extern "C" void kernel_launch(void* const* d_in, const int* in_sizes, int n_in,
                              void* d_out, int out_size) {
    const float* x     = (const float*)d_in[0];
    // d_in[1] = mask: known causal tril, applied analytically
    const float* w_qkv = (const float*)d_in[2];
    const float* w_out = (const float*)d_in[3];
    float* out = (float*)d_out;

    __half *qkvh, *qkvl, *xb, *wqkvb, *woutb, *attnb;
    cudaGetSymbolAddress((void**)&qkvh,  g_qkvh);
    cudaGetSymbolAddress((void**)&qkvl,  g_qkvl);
    cudaGetSymbolAddress((void**)&xb,    g_xb);
    cudaGetSymbolAddress((void**)&wqkvb, g_wqkvb);
    cudaGetSymbolAddress((void**)&woutb, g_woutb);
    cudaGetSymbolAddress((void**)&attnb, g_attnb);

    const int attn_smem = 2 * 2 * 64 * LDR * 2;      // 36864
    cudaFuncSetAttribute((const void*)attn_kernel,
                         cudaFuncAttributeMaxDynamicSharedMemorySize, attn_smem);

    // 0) fp32 -> fp16 operands
    split_kernel<true ><<<(MTOT * DM / 2) / 256, 256>>>(x, xb, MTOT * DM / 2);
    split_kernel<false><<<(QW * DM / 2) / 256, 256>>>(w_qkv, wqkvb, QW * DM / 2);
    cvt_kernel<<<(DM * DM / 2) / 256, 256>>>(w_out, woutb, DM * DM / 2);

    // 1) qkv = x @ w_qkv^T  (fp16; q 2-term K=2048, k/v 1-term K=1024)
    mma_gemm<QW, GK, true><<<dim3(QW / 128, MTOT / 128), 256>>>(
        xb, wqkvb, nullptr, qkvh, qkvl);

    // 2) causal flash attention (256-row blocks) -> fp16 hi A for GEMM3
    attn_kernel<<<dim3(SEQ / 256, NH, NB), 512, attn_smem>>>(qkvh, qkvl, attnb);

    // 3) out = attn @ w_out^T  (fp16 1-term, K=1024)
    mma_gemm<DM, DM, false><<<dim3(DM / 128, MTOT / 128), 256>>>(
        attnb, woutb, out, nullptr, nullptr);
}

// round 15
// speedup vs baseline: 1.0202x; 1.0202x over previous
#include <cuda_runtime.h>
#include <cuda_fp16.h>
#include <math.h>
#include <cstdint>

#define SEQ 2048
#define DM  1024
#define HD  64
#define NH  16
#define NB  2
#define MTOT (NB*SEQ)     // 4096
#define GK   (2*DM)       // 2048 = 2-term fp16 split K (GEMM1 q-columns)
#define QW   (3*DM)       // qkv output row stride
#define BK   32
#define LDA  40           // gemm smem row stride (fp16)
#define LDR  72           // attn smem row stride (fp16)
#define QSC  (0.125f * 1.44269504088896f)   // head scale * log2(e): exp2 softmax

// scratch (__device__ globals: allocation-free rule)
__device__ __half  g_qkvh [(size_t)MTOT * QW];    // qkv hi (q pre-scaled to log2 domain)
__device__ __half  g_qkvl [(size_t)MTOT * QW];    // qkv lo (only q part written/read)
__device__ __half  g_xb   [(size_t)MTOT * GK];    // A' of GEMM1 [hi,lo]
__device__ __half  g_wqkvb[(size_t)QW   * GK];    // B' of GEMM1 [wh,wh]
__device__ __half  g_woutb[(size_t)DM   * DM];    // B of GEMM3 [wh] (K=1024)
__device__ __half  g_attnb[(size_t)MTOT * DM];    // A of GEMM3 [hi] (K=1024)

__device__ __forceinline__ uint32_t smem_u32(const void* p) {
    uint32_t a;
    asm("{ .reg .u64 t; cvta.to.shared.u64 t, %1; cvt.u32.u64 %0, t; }"
        : "=r"(a) : "l"(p));
    return a;
}

__device__ __forceinline__ void split2h(float x, float y, uint32_t& hi, uint32_t& lo) {
    __half2 h, l;
    h.x = __float2half(x);
    h.y = __float2half(y);
    l.x = __float2half(x - __half2float(h.x));
    l.y = __float2half(y - __half2float(h.y));
    hi = *(uint32_t*)&h;
    lo = *(uint32_t*)&l;
}

__device__ __forceinline__ uint32_t cvt2h(float x, float y) {
    __half2 h;
    h.x = __float2half(x);
    h.y = __float2half(y);
    return *(uint32_t*)&h;
}

#define MMA_OP(d, a, b)                                                        \
    asm volatile(                                                              \
        "mma.sync.aligned.m16n8k16.row.col.f32.f16.f16.f32 "                   \
        "{%0,%1,%2,%3}, {%4,%5,%6,%7}, {%8,%9}, {%0,%1,%2,%3};"                \
        : "+f"((d)[0]), "+f"((d)[1]), "+f"((d)[2]), "+f"((d)[3])               \
        : "r"((a)[0]), "r"((a)[1]), "r"((a)[2]), "r"((a)[3]),                  \
          "r"((b)[0]), "r"((b)[1]))

#define LDSM_X4(r, addr)                                                       \
    asm volatile("ldmatrix.sync.aligned.m8n8.x4.shared.b16 {%0,%1,%2,%3}, [%4];" \
                 : "=r"((r)[0]), "=r"((r)[1]), "=r"((r)[2]), "=r"((r)[3])      \
                 : "r"(addr))

#define LDSM_X4_T(r, addr)                                                     \
    asm volatile("ldmatrix.sync.aligned.m8n8.x4.trans.shared.b16 {%0,%1,%2,%3}, [%4];" \
                 : "=r"((r)[0]), "=r"((r)[1]), "=r"((r)[2]), "=r"((r)[3])      \
                 : "r"(addr))

#define CP16(dst, src)                                                         \
    asm volatile("cp.async.cg.shared.global [%0], [%1], 16;" :: "r"(dst), "l"(src))

// ---------------------------------------------------------------------------
// fp32 -> fp16 split; A-style = [hi, lo] (stride GK), B-style = [wh, wh]
// ---------------------------------------------------------------------------
template<bool ASTYLE>
__global__ __launch_bounds__(256)
void split_kernel(const float* __restrict__ src, __half* __restrict__ dst,
                  int n2) {   // n2 = n/2
    int i = blockIdx.x * 256 + threadIdx.x;
    if (i >= n2) return;
    int e = i * 2;
    int r = e >> 10, k = e & 1023;
    float2 v = *(const float2*)(src + e);
    uint32_t h2, l2;
    split2h(v.x, v.y, h2, l2);
    __half* d = dst + (size_t)r * GK + k;
    if (ASTYLE) { *(uint32_t*)(d) = h2; *(uint32_t*)(d + 1024) = l2; }
    else        { *(uint32_t*)(d) = h2; *(uint32_t*)(d + 1024) = h2; }
}

// plain fp32 -> fp16 convert (row-major, same shape)
__global__ __launch_bounds__(256)
void cvt_kernel(const float* __restrict__ src, __half* __restrict__ dst, int n2) {
    int i = blockIdx.x * 256 + threadIdx.x;
    if (i >= n2) return;
    float2 v = *(const float2*)(src + i * 2);
    *(uint32_t*)(dst + i * 2) = cvt2h(v.x, v.y);
}

// ---------------------------------------------------------------------------
// fp16 NT GEMM via mma.sync — R3 geometry/schedule (best measured):
// 128x128 CTA, 8 warps (64x32 warp tile), BK=32, 2-stage cp.async,
// wait_group 1 + dual __syncthreads per chunk.
// SPLIT mode (GEMM1): k and v column blocks (bn>=1024) use only the hi half
// of K (1-term); lo-plane written for q columns only. q pre-scaled by QSC.
// ---------------------------------------------------------------------------
template<int NTOT, int KTOT, bool SPLIT>
__global__ __launch_bounds__(256)
void mma_gemm(const __half* __restrict__ A,
              const __half* __restrict__ B,
              float* __restrict__ C,
              __half* __restrict__ Ch,
              __half* __restrict__ Cl) {
    __shared__ __half As[2 * 128 * LDA];
    __shared__ __half Bs[2 * 128 * LDA];
    const int tid = threadIdx.x;
    const int lane = tid & 31;
    const int wid = tid >> 5;
    const int wm = wid & 1;
    const int wn = wid >> 1;
    const int bm = blockIdx.y * 128;
    const int bn = blockIdx.x * 128;

    // k and v columns need only the hi (1-term) half of K
    const int nch = (SPLIT && bn >= 1024) ? (KTOT / 2 / BK) : (KTOT / BK);

    float acc[4][4][4];
#pragma unroll
    for (int i = 0; i < 4; i++)
#pragma unroll
        for (int j = 0; j < 4; j++)
#pragma unroll
            for (int k = 0; k < 4; k++) acc[i][j][k] = 0.f;

    const int lrow = tid >> 1;
    const int lcol = (tid & 1) * 16;
    const __half* Ag = A + (size_t)(bm + lrow) * KTOT + lcol;
    const __half* Bg = B + (size_t)(bn + lrow) * KTOT + lcol;
    const uint32_t a_smem = smem_u32(As);
    const uint32_t b_smem = smem_u32(Bs);
    const uint32_t st_off = (uint32_t)(lrow * LDA + lcol) * 2;
    const uint32_t stage_b = 128 * LDA * 2;

#define LOAD_STAGE(s, kc) do {                                                 \
        const char* ga = (const char*)(Ag + (size_t)(kc) * BK);                \
        const char* gb = (const char*)(Bg + (size_t)(kc) * BK);                \
        uint32_t sa = a_smem + (s) * stage_b + st_off;                         \
        uint32_t sb = b_smem + (s) * stage_b + st_off;                         \
        CP16(sa, ga); CP16(sa + 16, ga + 16);                                  \
        CP16(sb, gb); CP16(sb + 16, gb + 16);                                  \
        asm volatile("cp.async.commit_group;" ::: "memory");                   \
    } while (0)

    const int lr16 = lane & 15;
    const int lhi  = lane >> 4;

    LOAD_STAGE(0, 0);

    for (int c = 0; c < nch; ++c) {
        const int s = c & 1;
        if (c + 1 < nch) {
            LOAD_STAGE(s ^ 1, c + 1);
            asm volatile("cp.async.wait_group 1;" ::: "memory");
        } else {
            asm volatile("cp.async.wait_group 0;" ::: "memory");
        }
        __syncthreads();

        const uint32_t ab = a_smem + s * stage_b;
        const uint32_t bb = b_smem + s * stage_b;
#pragma unroll
        for (int kk = 0; kk < 2; kk++) {
            uint32_t a[4][4];
#pragma unroll
            for (int mi = 0; mi < 4; mi++) {
                uint32_t addr = ab + (uint32_t)((wm * 64 + mi * 16 + lr16) * LDA
                                                + kk * 16 + lhi * 8) * 2;
                LDSM_X4(a[mi], addr);
            }
            uint32_t b[4][2];
#pragma unroll
            for (int g = 0; g < 2; g++) {
                uint32_t r[4];
                uint32_t addr = bb + (uint32_t)((wn * 32 + g * 16 + lr16) * LDA
                                                + kk * 16 + lhi * 8) * 2;
                LDSM_X4(r, addr);
                b[g * 2 + 0][0] = r[0]; b[g * 2 + 0][1] = r[2];
                b[g * 2 + 1][0] = r[1]; b[g * 2 + 1][1] = r[3];
            }
#pragma unroll
            for (int mi = 0; mi < 4; mi++)
#pragma unroll
                for (int ni = 0; ni < 4; ni++)
                    MMA_OP(acc[mi][ni], a[mi], b[ni]);
        }
        __syncthreads();
    }
#undef LOAD_STAGE

    const int er = lane >> 2;
    const int ec = (lane & 3) * 2;
#pragma unroll
    for (int mi = 0; mi < 4; mi++) {
#pragma unroll
        for (int ni = 0; ni < 4; ni++) {
            const int row = bm + wm * 64 + mi * 16 + er;
            const int col = bn + wn * 32 + ni * 8 + ec;
            if (SPLIT) {
                const float sc = (col < 1024) ? QSC : 1.0f;   // log2-domain q scale
                const bool wlo = (col < 1024);                // lo plane: q only
                uint32_t h2, l2;
                split2h(acc[mi][ni][0] * sc, acc[mi][ni][1] * sc, h2, l2);
                *(uint32_t*)(Ch + (size_t)row * NTOT + col) = h2;
                if (wlo) *(uint32_t*)(Cl + (size_t)row * NTOT + col) = l2;
                split2h(acc[mi][ni][2] * sc, acc[mi][ni][3] * sc, h2, l2);
                *(uint32_t*)(Ch + (size_t)(row + 8) * NTOT + col) = h2;
                if (wlo) *(uint32_t*)(Cl + (size_t)(row + 8) * NTOT + col) = l2;
            } else {
                float2 v0 = make_float2(acc[mi][ni][0], acc[mi][ni][1]);
                float2 v1 = make_float2(acc[mi][ni][2], acc[mi][ni][3]);
                *(float2*)(C + (size_t)row * NTOT + col) = v0;
                *(float2*)(C + (size_t)(row + 8) * NTOT + col) = v1;
            }
        }
    }
}

// ---------------------------------------------------------------------------
// Tensor-core flash attention (causal), fp16, exp2-domain softmax.
// S = (qh+ql)·kh  (2-term q: exp-amplified path keeps precision)
// O = ph·vh       (1-term: post-softmax linear path)
// Block = 128 q-rows x (head,batch), 8 warps (16 rows each), 256 threads
// (R13 geometry: two independent CTAs per SM overlap barrier stalls).
// K/V 64-key hi tiles double-buffered via cp.async. Descending-qt order.
// ---------------------------------------------------------------------------
#define NEG_BIG (-1e30f)

__global__ __launch_bounds__(256)
void attn_kernel(const __half* __restrict__ qkvh,
                 const __half* __restrict__ qkvl,
                 __half* __restrict__ attnb) {
    extern __shared__ __half smk[];
    const uint32_t s_base = smem_u32(smk);
    const uint32_t tpb = 64 * LDR * 2;   // 9216 B per tensor
    const uint32_t spb = 2 * tpb;        // per stage (Kh, Vh)

    const int tid  = threadIdx.x;
    const int lane = tid & 31;
    const int wid  = tid >> 5;           // 0..7
    const int qt = (int)gridDim.x - 1 - (int)blockIdx.x;  // heaviest first
    const int h  = blockIdx.y;
    const int b  = blockIdx.z;

    const int lr16 = lane & 15;
    const int lhi  = lane >> 4;
    const int er   = lane >> 2;
    const int ec   = (lane & 3) * 2;

    const int qrow0 = qt * 128 + wid * 16;

    // ---- Q hi/lo fragments (pre-scaled to log2 domain) held in regs ----
    uint32_t qh[4][4], ql[4][4];
    {
        const __half* qbh = qkvh + ((size_t)b * SEQ) * QW + h * HD;
        const __half* qbl = qkvl + ((size_t)b * SEQ) * QW + h * HD;
#pragma unroll
        for (int kc = 0; kc < 4; kc++) {
#pragma unroll
            for (int p = 0; p < 4; p++) {
                const int r = qrow0 + er + (p & 1) * 8;
                const int c = kc * 16 + ec + (p >> 1) * 8;
                qh[kc][p] = *(const uint32_t*)(qbh + (size_t)r * QW + c);
                ql[kc][p] = *(const uint32_t*)(qbl + (size_t)r * QW + c);
            }
        }
    }

    float m0 = NEG_BIG, m1 = NEG_BIG, l0 = 0.f, l1 = 0.f;
    float acc[8][4];
#pragma unroll
    for (int nb = 0; nb < 8; nb++)
#pragma unroll
        for (int j = 0; j < 4; j++) acc[nb][j] = 0.f;

    const int krow = tid >> 2;
    const int kch  = (tid & 3) * 2;

#define KV_LOAD(s, jt_) do {                                                   \
        size_t gr = ((size_t)b * SEQ + (size_t)(jt_) * 64 + krow) * QW         \
                    + h * HD + kch * 8;                                        \
        const char* khg = (const char*)(qkvh + gr + 1024);                     \
        const char* vhg = (const char*)(qkvh + gr + 2048);                     \
        uint32_t d = s_base + (s) * spb + (uint32_t)(krow * LDR * 2 + kch * 16); \
        _Pragma("unroll")                                                      \
        for (int u = 0; u < 2; u++) {                                          \
            CP16(d + u * 16 + 0 * tpb, khg + u * 16);                          \
            CP16(d + u * 16 + 1 * tpb, vhg + u * 16);                          \
        }                                                                      \
        asm volatile("cp.async.commit_group;" ::: "memory");                   \
    } while (0)

    const int ntiles = 2 * qt + 2;
    KV_LOAD(0, 0);

    for (int jt = 0; jt < ntiles; ++jt) {
        const int s = jt & 1;
        asm volatile("cp.async.wait_group 0;" ::: "memory");
        __syncthreads();
        if (jt + 1 < ntiles) KV_LOAD(s ^ 1, jt + 1);

        if (jt * 64 <= qrow0 + 15) {   // warp has unmasked work in this tile
            const uint32_t kh_s = s_base + s * spb;
            const uint32_t vh_s = kh_s + tpb;

            // ---- S = Qs @ Kh^T (qh + ql terms), log2-domain logits ----
            float sv[8][4];
#pragma unroll
            for (int nb = 0; nb < 8; nb++)
#pragma unroll
                for (int j = 0; j < 4; j++) sv[nb][j] = 0.f;

#pragma unroll
            for (int kc = 0; kc < 4; kc++) {
                uint32_t bh[8][2];
#pragma unroll
                for (int g = 0; g < 4; g++) {
                    uint32_t r4[4];
                    uint32_t off = (uint32_t)((g * 16 + lr16) * LDR
                                              + kc * 16 + lhi * 8) * 2;
                    LDSM_X4(r4, kh_s + off);
                    bh[2*g][0] = r4[0]; bh[2*g][1] = r4[2];
                    bh[2*g+1][0] = r4[1]; bh[2*g+1][1] = r4[3];
                }
#pragma unroll
                for (int nb = 0; nb < 8; nb++) {
                    MMA_OP(sv[nb], qh[kc], bh[nb]);
                    MMA_OP(sv[nb], ql[kc], bh[nb]);
                }
            }

            // ---- causal mask where tile crosses diagonal ----
            if (jt * 64 + 63 > qrow0) {
                const int r0g = qrow0 + er, r1g = r0g + 8;
#pragma unroll
                for (int nb = 0; nb < 8; nb++) {
                    const int c0g = jt * 64 + nb * 8 + ec;
                    if (c0g     > r0g) sv[nb][0] = NEG_BIG;
                    if (c0g + 1 > r0g) sv[nb][1] = NEG_BIG;
                    if (c0g     > r1g) sv[nb][2] = NEG_BIG;
                    if (c0g + 1 > r1g) sv[nb][3] = NEG_BIG;
                }
            }

            // ---- online softmax (base-2) ----
            float mt0 = NEG_BIG, mt1 = NEG_BIG;
#pragma unroll
            for (int nb = 0; nb < 8; nb++) {
                mt0 = fmaxf(mt0, fmaxf(sv[nb][0], sv[nb][1]));
                mt1 = fmaxf(mt1, fmaxf(sv[nb][2], sv[nb][3]));
            }
            mt0 = fmaxf(mt0, __shfl_xor_sync(0xffffffffu, mt0, 1));
            mt0 = fmaxf(mt0, __shfl_xor_sync(0xffffffffu, mt0, 2));
            mt1 = fmaxf(mt1, __shfl_xor_sync(0xffffffffu, mt1, 1));
            mt1 = fmaxf(mt1, __shfl_xor_sync(0xffffffffu, mt1, 2));
            const float nm0 = fmaxf(m0, mt0), nm1 = fmaxf(m1, mt1);
            const float a0 = exp2f(m0 - nm0), a1 = exp2f(m1 - nm1);
            m0 = nm0; m1 = nm1;
            float sum0 = 0.f, sum1 = 0.f;
#pragma unroll
            for (int nb = 0; nb < 8; nb++) {
                sv[nb][0] = exp2f(sv[nb][0] - nm0);
                sv[nb][1] = exp2f(sv[nb][1] - nm0);
                sv[nb][2] = exp2f(sv[nb][2] - nm1);
                sv[nb][3] = exp2f(sv[nb][3] - nm1);
                sum0 += sv[nb][0] + sv[nb][1];
                sum1 += sv[nb][2] + sv[nb][3];
            }
            sum0 += __shfl_xor_sync(0xffffffffu, sum0, 1);
            sum0 += __shfl_xor_sync(0xffffffffu, sum0, 2);
            sum1 += __shfl_xor_sync(0xffffffffu, sum1, 1);
            sum1 += __shfl_xor_sync(0xffffffffu, sum1, 2);
            l0 = l0 * a0 + sum0;
            l1 = l1 * a1 + sum1;
#pragma unroll
            for (int nb = 0; nb < 8; nb++) {
                acc[nb][0] *= a0; acc[nb][1] *= a0;
                acc[nb][2] *= a1; acc[nb][3] *= a1;
            }

            // ---- pack P into fp16 A-fragments (hi only) ----
            uint32_t ah[4][4];
#pragma unroll
            for (int g = 0; g < 4; g++) {
                ah[g][0] = cvt2h(sv[2*g][0],   sv[2*g][1]);
                ah[g][1] = cvt2h(sv[2*g][2],   sv[2*g][3]);
                ah[g][2] = cvt2h(sv[2*g+1][0], sv[2*g+1][1]);
                ah[g][3] = cvt2h(sv[2*g+1][2], sv[2*g+1][3]);
            }

            // ---- O += Ph @ Vh (1-term, linear path) ----
#pragma unroll
            for (int g = 0; g < 4; g++) {
                uint32_t bvh[8][2];
#pragma unroll
                for (int du = 0; du < 4; du++) {
                    uint32_t r4[4];
                    uint32_t off = (uint32_t)((g * 16 + lr16) * LDR
                                              + du * 16 + lhi * 8) * 2;
                    LDSM_X4_T(r4, vh_s + off);
                    bvh[2*du][0] = r4[0]; bvh[2*du][1] = r4[1];
                    bvh[2*du+1][0] = r4[2]; bvh[2*du+1][1] = r4[3];
                }
#pragma unroll
                for (int nb = 0; nb < 8; nb++)
                    MMA_OP(acc[nb], ah[g], bvh[nb]);
            }
        }
    }
#undef KV_LOAD

    // ---- epilogue: normalize, fp16 hi write (K=1024 for GEMM3) ----
    const float inv0 = 1.f / l0, inv1 = 1.f / l1;
#pragma unroll
    for (int nb = 0; nb < 8; nb++) {
        const int col = h * HD + nb * 8 + ec;
        __half* p0 = attnb + ((size_t)b * SEQ + qrow0 + er) * DM + col;
        *(uint32_t*)(p0) = cvt2h(acc[nb][0] * inv0, acc[nb][1] * inv0);
        __half* p1 = p0 + (size_t)8 * DM;
        *(uint32_t*)(p1) = cvt2h(acc[nb][2] * inv1, acc[nb][3] * inv1);
    }
}

// ---------------------------------------------------------------------------
extern "C" void kernel_launch(void* const* d_in, const int* in_sizes, int n_in,
                              void* d_out, int out_size) {
    const float* x     = (const float*)d_in[0];
    // d_in[1] = mask: known causal tril, applied analytically
    const float* w_qkv = (const float*)d_in[2];
    const float* w_out = (const float*)d_in[3];
    float* out = (float*)d_out;

    __half *qkvh, *qkvl, *xb, *wqkvb, *woutb, *attnb;
    cudaGetSymbolAddress((void**)&qkvh,  g_qkvh);
    cudaGetSymbolAddress((void**)&qkvl,  g_qkvl);
    cudaGetSymbolAddress((void**)&xb,    g_xb);
    cudaGetSymbolAddress((void**)&wqkvb, g_wqkvb);
    cudaGetSymbolAddress((void**)&woutb, g_woutb);
    cudaGetSymbolAddress((void**)&attnb, g_attnb);

    const int attn_smem = 2 * 2 * 64 * LDR * 2;      // 36864
    cudaFuncSetAttribute((const void*)attn_kernel,
                         cudaFuncAttributeMaxDynamicSharedMemorySize, attn_smem);

    // 0) fp32 -> fp16 operands
    split_kernel<true ><<<(MTOT * DM / 2) / 256, 256>>>(x, xb, MTOT * DM / 2);
    split_kernel<false><<<(QW * DM / 2) / 256, 256>>>(w_qkv, wqkvb, QW * DM / 2);
    cvt_kernel<<<(DM * DM / 2) / 256, 256>>>(w_out, woutb, DM * DM / 2);

    // 1) qkv = x @ w_qkv^T  (fp16; q 2-term K=2048, k/v 1-term K=1024)
    mma_gemm<QW, GK, true><<<dim3(QW / 128, MTOT / 128), 256>>>(
        xb, wqkvb, nullptr, qkvh, qkvl);

    // 2) causal flash attention (128-row blocks, exp2) -> fp16 hi A for GEMM3
    attn_kernel<<<dim3(SEQ / 128, NH, NB), 256, attn_smem>>>(qkvh, qkvl, attnb);

    // 3) out = attn @ w_out^T  (fp16 1-term, K=1024)
    mma_gemm<DM, DM, false><<<dim3(DM / 128, MTOT / 128), 256>>>(
        attnb, woutb, out, nullptr, nullptr);
}